// round 12
// baseline (speedup 1.0000x reference)
#include <cuda_runtime.h>
#include <cuda_bf16.h>
#include <math.h>
#include <cstdint>

// Problem constants
#define NB   32      // batch
#define SL   256     // sequence length
#define DD   1024    // input dim
#define HH   1024    // hidden dim
#define NBLK 128     // persistent blocks; each owns an 8-col slice of BOTH dirs
#define TPB  512

// ---------------------------------------------------------------------------
// Scratch (device globals)
// ---------------------------------------------------------------------------
__device__ float g_xh[(size_t)8 * SL * NB * HH];   // 268 MB: xh[g][s][n][h]
__device__ int   g_flag[2][NBLK];                  // per-dir, per-block progress
// bf16 split operands for the input GEMM
__device__ __nv_bfloat16 g_xa_hi[(size_t)NB * SL * DD];
__device__ __nv_bfloat16 g_xa_lo[(size_t)NB * SL * DD];
__device__ __nv_bfloat16 g_wt_hi[(size_t)8 * HH * DD];   // W_ih [g][n][k]
__device__ __nv_bfloat16 g_wt_lo[(size_t)8 * HH * DD];
// W_hh in mma-fragment-major layout: [g(8)][nb(128)][kb(64)][lane(32)] uint2
__device__ uint2 g_wrhifrag[8][128][64][32];
__device__ uint2 g_wrlofrag[8][128][64][32];
// h state in A-fragment-major layout, double-buffered by parity:
//   [par][dir][hl][kb(64)][mb(2)][lane(32)] uint4 (regs a0..a3)
__device__ uint4 g_hfrag[2][2][2][64][2][32];

__device__ __forceinline__ float sigmf(float v) {
    return 1.0f / (1.0f + expf(-v));
}

// mma.sync m16n8k16 bf16, fp32 accumulate
__device__ __forceinline__ void mma16816(float* c, const uint32_t* a,
                                         const uint32_t* b) {
    asm volatile(
        "mma.sync.aligned.m16n8k16.row.col.f32.bf16.bf16.f32 "
        "{%0,%1,%2,%3}, {%4,%5,%6,%7}, {%8,%9}, {%0,%1,%2,%3};"
        : "+f"(c[0]), "+f"(c[1]), "+f"(c[2]), "+f"(c[3])
        : "r"(a[0]), "r"(a[1]), "r"(a[2]), "r"(a[3]), "r"(b[0]), "r"(b[1]));
}

// ---------------------------------------------------------------------------
// Kernel 0: zero init of h fragments and flags
// ---------------------------------------------------------------------------
__global__ void zero_state_kernel() {
    int idx = blockIdx.x * blockDim.x + threadIdx.x;
    uint4* hf = &g_hfrag[0][0][0][0][0][0];
    int total = 2 * 2 * 2 * 64 * 2 * 32;      // 16384 uint4
    for (int i = idx; i < total; i += gridDim.x * blockDim.x)
        hf[i] = make_uint4(0, 0, 0, 0);
    int* fl = &g_flag[0][0];
    for (int i = idx; i < 2 * NBLK; i += gridDim.x * blockDim.x) fl[i] = 0;
}

// ---------------------------------------------------------------------------
// Kernel A: convert x -> bf16 hi/lo
// ---------------------------------------------------------------------------
__global__ __launch_bounds__(256)
void convert_x_kernel(const float* __restrict__ x) {
    const size_t total4 = (size_t)NB * SL * DD / 4;
    for (size_t i = blockIdx.x * 256 + threadIdx.x; i < total4;
         i += (size_t)gridDim.x * 256) {
        float4 v = *(const float4*)(x + i * 4);
        __nv_bfloat16 h0 = __float2bfloat16_rn(v.x);
        __nv_bfloat16 h1 = __float2bfloat16_rn(v.y);
        __nv_bfloat16 h2 = __float2bfloat16_rn(v.z);
        __nv_bfloat16 h3 = __float2bfloat16_rn(v.w);
        __nv_bfloat16 l0 = __float2bfloat16_rn(v.x - __bfloat162float(h0));
        __nv_bfloat16 l1 = __float2bfloat16_rn(v.y - __bfloat162float(h1));
        __nv_bfloat16 l2 = __float2bfloat16_rn(v.z - __bfloat162float(h2));
        __nv_bfloat16 l3 = __float2bfloat16_rn(v.w - __bfloat162float(h3));
        __nv_bfloat162 hh0 = __halves2bfloat162(h0, h1);
        __nv_bfloat162 hh1 = __halves2bfloat162(h2, h3);
        __nv_bfloat162 ll0 = __halves2bfloat162(l0, l1);
        __nv_bfloat162 ll1 = __halves2bfloat162(l2, l3);
        *(uint2*)(g_xa_hi + i * 4) = make_uint2(*(uint32_t*)&hh0, *(uint32_t*)&hh1);
        *(uint2*)(g_xa_lo + i * 4) = make_uint2(*(uint32_t*)&ll0, *(uint32_t*)&ll1);
    }
}

// ---------------------------------------------------------------------------
// Kernel B: transpose + convert W_ih -> [g][n][k] bf16 hi/lo (row-major)
// ---------------------------------------------------------------------------
__global__ void convert_w_kernel(const float* __restrict__ w) {
    __shared__ float tile[32][33];
    const int g  = blockIdx.z;
    const int k0 = blockIdx.x * 32;
    const int n0 = blockIdx.y * 32;
    const int tx = threadIdx.x, ty = threadIdx.y;   // (32, 8)
    const float* W = w + ((size_t)g << 20);
#pragma unroll
    for (int i = 0; i < 4; i++)
        tile[ty + 8 * i][tx] = W[(size_t)(k0 + ty + 8 * i) * HH + n0 + tx];
    __syncthreads();
#pragma unroll
    for (int i = 0; i < 4; i++) {
        float v = tile[tx][ty + 8 * i];
        __nv_bfloat16 hi = __float2bfloat16_rn(v);
        __nv_bfloat16 lo = __float2bfloat16_rn(v - __bfloat162float(hi));
        size_t idx = ((size_t)g << 20) + (size_t)(n0 + ty + 8 * i) * DD + k0 + tx;
        g_wt_hi[idx] = hi;
        g_wt_lo[idx] = lo;
    }
}

// ---------------------------------------------------------------------------
// Kernel B2: W_hh -> fragment-major bf16 hi/lo
// ---------------------------------------------------------------------------
__global__ __launch_bounds__(256)
void convert_whh_frag_kernel(const float* __restrict__ whh) {
    const int g  = blockIdx.x;          // 0..7
    const int nb = blockIdx.y;          // 0..127
    const int tid = threadIdx.x;
    const int nn  = tid & 7;            // row within nb
    const int kp0 = tid >> 3;           // 0..31
    const int n   = nb * 8 + nn;
    const float* W = whh + ((size_t)g << 20);   // [k][n]

    for (int iter = 0; iter < 16; iter++) {
        int kp = iter * 32 + kp0;       // 0..511
        int k  = kp * 2;
        float v0 = W[(size_t)k * HH + n];
        float v1 = W[(size_t)(k + 1) * HH + n];
        __nv_bfloat16 h0 = __float2bfloat16_rn(v0);
        __nv_bfloat16 h1 = __float2bfloat16_rn(v1);
        __nv_bfloat16 l0 = __float2bfloat16_rn(v0 - __bfloat162float(h0));
        __nv_bfloat16 l1 = __float2bfloat16_rn(v1 - __bfloat162float(h1));
        __nv_bfloat162 hp = __halves2bfloat162(h0, h1);
        __nv_bfloat162 lp = __halves2bfloat162(l0, l1);
        int kb   = k >> 4;
        int lane = nn * 4 + ((k & 7) >> 1);
        int reg  = (k >> 3) & 1;
        ((uint32_t*)&g_wrhifrag[g][nb][kb][lane])[reg] = *(uint32_t*)&hp;
        ((uint32_t*)&g_wrlofrag[g][nb][kb][lane])[reg] = *(uint32_t*)&lp;
    }
}

// ---------------------------------------------------------------------------
// Kernel C: mma.sync bf16x3 input-projection GEMM (proven in R6).
// ---------------------------------------------------------------------------
#define ASTR 40

__global__ __launch_bounds__(256, 2)
void gemm_ih_mma_kernel(const float* __restrict__ bias) {
    __shared__ __nv_bfloat16 As_hi[128][ASTR];
    __shared__ __nv_bfloat16 As_lo[128][ASTR];
    __shared__ __nv_bfloat16 Bs_hi[64][ASTR];
    __shared__ __nv_bfloat16 Bs_lo[64][ASTR];

    const int g   = blockIdx.z;
    const int m0  = blockIdx.x * 128;
    const int n0  = blockIdx.y * 64;
    const int tid = threadIdx.x;
    const int wid = tid >> 5;
    const int lid = tid & 31;
    const int wm  = wid & 3;
    const int wn  = wid >> 2;

    const __nv_bfloat16* a_hi = g_xa_hi;
    const __nv_bfloat16* a_lo = g_xa_lo;
    const __nv_bfloat16* b_hi = g_wt_hi + ((size_t)g << 20);
    const __nv_bfloat16* b_lo = g_wt_lo + ((size_t)g << 20);

    float acc[2][4][4];
#pragma unroll
    for (int mt = 0; mt < 2; mt++)
#pragma unroll
        for (int nt = 0; nt < 4; nt++)
#pragma unroll
            for (int r = 0; r < 4; r++) acc[mt][nt][r] = 0.0f;

    const int fq = lid >> 2;
    const int fk = (lid & 3) * 2;

    for (int k0 = 0; k0 < DD; k0 += 32) {
        __syncthreads();
#pragma unroll
        for (int s = 0; s < 2; s++) {
            int lin = tid + s * 256;
            int row = lin >> 2;
            int kq  = (lin & 3) * 8;
            *(uint4*)&As_hi[row][kq] =
                *(const uint4*)(a_hi + (size_t)(m0 + row) * DD + k0 + kq);
            *(uint4*)&As_lo[row][kq] =
                *(const uint4*)(a_lo + (size_t)(m0 + row) * DD + k0 + kq);
        }
        {
            int row = tid >> 2;
            int kq  = (tid & 3) * 8;
            *(uint4*)&Bs_hi[row][kq] =
                *(const uint4*)(b_hi + (size_t)(n0 + row) * DD + k0 + kq);
            *(uint4*)&Bs_lo[row][kq] =
                *(const uint4*)(b_lo + (size_t)(n0 + row) * DD + k0 + kq);
        }
        __syncthreads();

#pragma unroll
        for (int ks = 0; ks < 32; ks += 16) {
            uint32_t Ah[2][4], Al[2][4], Bh[4][2], Bl[4][2];
#pragma unroll
            for (int mt = 0; mt < 2; mt++) {
                int mb = wm * 32 + mt * 16;
                Ah[mt][0] = *(const uint32_t*)&As_hi[mb + fq][ks + fk];
                Ah[mt][1] = *(const uint32_t*)&As_hi[mb + fq + 8][ks + fk];
                Ah[mt][2] = *(const uint32_t*)&As_hi[mb + fq][ks + fk + 8];
                Ah[mt][3] = *(const uint32_t*)&As_hi[mb + fq + 8][ks + fk + 8];
                Al[mt][0] = *(const uint32_t*)&As_lo[mb + fq][ks + fk];
                Al[mt][1] = *(const uint32_t*)&As_lo[mb + fq + 8][ks + fk];
                Al[mt][2] = *(const uint32_t*)&As_lo[mb + fq][ks + fk + 8];
                Al[mt][3] = *(const uint32_t*)&As_lo[mb + fq + 8][ks + fk + 8];
            }
#pragma unroll
            for (int nt = 0; nt < 4; nt++) {
                int nb = wn * 32 + nt * 8;
                Bh[nt][0] = *(const uint32_t*)&Bs_hi[nb + fq][ks + fk];
                Bh[nt][1] = *(const uint32_t*)&Bs_hi[nb + fq][ks + fk + 8];
                Bl[nt][0] = *(const uint32_t*)&Bs_lo[nb + fq][ks + fk];
                Bl[nt][1] = *(const uint32_t*)&Bs_lo[nb + fq][ks + fk + 8];
            }
#pragma unroll
            for (int mt = 0; mt < 2; mt++)
#pragma unroll
                for (int nt = 0; nt < 4; nt++) {
                    mma16816(acc[mt][nt], Ah[mt], Bh[nt]);
                    mma16816(acc[mt][nt], Ah[mt], Bl[nt]);
                    mma16816(acc[mt][nt], Al[mt], Bh[nt]);
                }
        }
    }

#pragma unroll
    for (int mt = 0; mt < 2; mt++) {
#pragma unroll
        for (int nt = 0; nt < 4; nt++) {
            int col = n0 + wn * 32 + nt * 8 + (lid & 3) * 2;
            float2 bz = *(const float2*)&bias[g * HH + col];
#pragma unroll
            for (int half = 0; half < 2; half++) {
                int row  = m0 + wm * 32 + mt * 16 + fq + half * 8;
                int nidx = row >> 8;
                int s    = row & 255;
                size_t base = ((((size_t)g * SL + s) * NB + nidx) << 10) + col;
                *(float2*)&g_xh[base] = make_float2(
                    acc[mt][nt][half * 2 + 0] + bz.x,
                    acc[mt][nt][half * 2 + 1] + bz.y);
            }
        }
    }
}

// ---------------------------------------------------------------------------
// Kernel D: persistent recurrence, dual-direction interleaved.
// 128 blocks x 512 threads. Block bid owns 8 h-cols (bid*8..+7) x 4 gates of
// BOTH directions. Per step: wait_f -> GEMM_f -> cell_f -> flag_f -> wait_b
// -> GEMM_b -> cell_b -> flag_b. Each dir's barrier latency hides behind the
// other dir's GEMM. W_hi frags (both dirs, 128KB) resident in smem; W_lo + A
// frags streamed from fragment-major global (ldcg). Warp (kq,nq,cp).
// ---------------------------------------------------------------------------
// smem: [0,131072) W_hi frags, slab g=0..7 (dir*4+gate), nb = bid
//       [131072, +34816) PART [8][32][34] f32 (shared f/b, serialized)
#define SM_TOTAL 165888
#define WHIF_OFF(g, kb, lane)  ((uint32_t)((((g) * 64 + (kb)) * 32 + (lane)) * 8))
#define PART_OFF(p, row, col)  ((uint32_t)(131072 + (((p) * 32 + (row)) * 34 + (col)) * 4))

// One direction's GEMM for this block's 32 W rows (4 gates x 8 cols).
__device__ __forceinline__ void recur_gemm(char* smem, int dir, int par,
                                           int bid, int kq, int nq, int cp,
                                           int lid, float acc[2][2][4]) {
#pragma unroll
    for (int mt = 0; mt < 2; mt++)
#pragma unroll
        for (int g = 0; g < 2; g++)
#pragma unroll
            for (int r = 0; r < 4; r++) acc[mt][g][r] = 0.0f;

    uint4 Ab[2][2][2];   // [buf][hl][mt]
    uint2 Wb[2][2];      // [buf][g]
    const int g2b = nq * 2;

    {
        int kb = kq * 16 + cp;
        Ab[0][0][0] = __ldcg(&g_hfrag[par][dir][0][kb][0][lid]);
        Ab[0][0][1] = __ldcg(&g_hfrag[par][dir][0][kb][1][lid]);
        Ab[0][1][0] = __ldcg(&g_hfrag[par][dir][1][kb][0][lid]);
        Ab[0][1][1] = __ldcg(&g_hfrag[par][dir][1][kb][1][lid]);
#pragma unroll
        for (int g = 0; g < 2; g++)
            Wb[0][g] = __ldcg(&g_wrlofrag[dir * 4 + g2b + g][bid][kb][lid]);
    }

    for (int j = 0; j < 8; j++) {
        const int b  = j & 1;
        const int kb = kq * 16 + cp + 2 * j;
        if (j < 7) {
            int kb2 = kb + 2;
            Ab[b ^ 1][0][0] = __ldcg(&g_hfrag[par][dir][0][kb2][0][lid]);
            Ab[b ^ 1][0][1] = __ldcg(&g_hfrag[par][dir][0][kb2][1][lid]);
            Ab[b ^ 1][1][0] = __ldcg(&g_hfrag[par][dir][1][kb2][0][lid]);
            Ab[b ^ 1][1][1] = __ldcg(&g_hfrag[par][dir][1][kb2][1][lid]);
#pragma unroll
            for (int g = 0; g < 2; g++)
                Wb[b ^ 1][g] = __ldcg(&g_wrlofrag[dir * 4 + g2b + g][bid][kb2][lid]);
        }
#pragma unroll
        for (int g = 0; g < 2; g++) {
            uint2 Bh = *(const uint2*)(smem + WHIF_OFF(dir * 4 + g2b + g, kb, lid));
            const uint32_t* Ah0 = (const uint32_t*)&Ab[b][0][0];
            const uint32_t* Ah1 = (const uint32_t*)&Ab[b][0][1];
            const uint32_t* Al0 = (const uint32_t*)&Ab[b][1][0];
            const uint32_t* Al1 = (const uint32_t*)&Ab[b][1][1];
            uint32_t bh[2] = {Bh.x, Bh.y};
            uint32_t bl[2] = {Wb[b][g].x, Wb[b][g].y};
            mma16816(acc[0][g], Ah0, bh);
            mma16816(acc[1][g], Ah1, bh);
            mma16816(acc[0][g], Ah0, bl);
            mma16816(acc[1][g], Ah1, bl);
            mma16816(acc[0][g], Al0, bh);
            mma16816(acc[1][g], Al1, bh);
        }
    }
}

__global__ __launch_bounds__(TPB, 1)
void bilstm_dual(const float* __restrict__ mask, float* __restrict__ out) {
    extern __shared__ char smem[];

    const int bid = blockIdx.x;           // 0..127: h-col slice bid*8..+7
    const int tid = threadIdx.x;
    const int wid = tid >> 5;
    const int lid = tid & 31;
    const int kq  = wid >> 2;             // K quarter
    const int nq  = (wid >> 1) & 1;       // gate pair
    const int cp  = wid & 1;              // kstep parity

    // ---- resident W_hi fragment copy: 8 slabs (g = dir*4+gate), nb = bid ----
#pragma unroll
    for (int s = 0; s < 8; s++) {
        const uint4* src = (const uint4*)&g_wrhifrag[s][bid][0][0];
        uint4* dst = (uint4*)(smem + s * 16384);
        for (int i = tid; i < 1024; i += TPB) dst[i] = src[i];
    }
    __syncthreads();

    // Cell assignment (threads 0..127): (n_c, col pair jj in slice)
    const int n_c  = tid >> 2;            // 0..31
    const int jj   = (tid & 3) * 2;       // 0,2,4,6
    const int hcol = bid * 8 + jj;
    const int kb_c   = bid >> 1;
    const int lane_c = (n_c & 7) * 4 + (jj >> 1);
    const int reg_c  = (bid & 1) * 2 + ((n_c >> 3) & 1);
    const int mb_c   = n_c >> 4;
    const bool do_cell = (tid < 128);
    float ccf[2] = {0.f, 0.f}, hrf[2] = {0.f, 0.f};
    float ccb[2] = {0.f, 0.f}, hrb[2] = {0.f, 0.f};
    const float* mrow = mask + n_c * SL;

    float acc[2][2][4];

    for (int t = 0; t < SL; t++) {
        const int par  = t & 1;
        const int posf = t;
        const int posb = SL - 1 - t;

        // Prefetch cell inputs for both dirs
        float2 xpf[4], xpb[4];
        float mf = 0.f, mb = 0.f;
        if (do_cell) {
#pragma unroll
            for (int g = 0; g < 4; ++g) {
                xpf[g] = __ldcg((const float2*)&g_xh[
                    ((((size_t)(0 * 4 + g) * SL + posf) * NB + n_c) << 10) + hcol]);
                xpb[g] = __ldcg((const float2*)&g_xh[
                    ((((size_t)(1 * 4 + g) * SL + posb) * NB + n_c) << 10) + hcol]);
            }
            mf = mrow[posf];
            mb = mrow[posb];
        }

        // ================= FORWARD half =================
        if (tid < NBLK) {
            while (*(volatile int*)&g_flag[0][tid] < t) __nanosleep(32);
            __threadfence();
        }
        __syncthreads();

        recur_gemm(smem, 0, par, bid, kq, nq, cp, lid, acc);

        {
            const int p  = kq * 2 + cp;
            const int fq = lid >> 2;
#pragma unroll
            for (int mt = 0; mt < 2; mt++)
#pragma unroll
                for (int g = 0; g < 2; g++) {
                    int col = (nq * 2 + g) * 8 + (lid & 3) * 2;
                    *(float2*)(smem + PART_OFF(p, mt * 16 + fq, col)) =
                        make_float2(acc[mt][g][0], acc[mt][g][1]);
                    *(float2*)(smem + PART_OFF(p, mt * 16 + fq + 8, col)) =
                        make_float2(acc[mt][g][2], acc[mt][g][3]);
                }
        }
        __syncthreads();

        if (do_cell) {
            float pre[4][2];
#pragma unroll
            for (int g = 0; g < 4; ++g) {
                float2 a2 = xpf[g];
#pragma unroll
                for (int p = 0; p < 8; ++p) {
                    float2 v = *(const float2*)(smem + PART_OFF(p, n_c, g * 8 + jj));
                    a2.x += v.x; a2.y += v.y;
                }
                pre[g][0] = a2.x; pre[g][1] = a2.y;
            }
#pragma unroll
            for (int j = 0; j < 2; ++j) {
                float f  = sigmf(pre[0][j]);
                float ii = sigmf(pre[1][j]);
                float o  = sigmf(pre[2][j]);
                ccf[j] = f * ccf[j] + ii * tanhf(pre[3][j]);
                float hn = o * tanhf(ccf[j]);
                hrf[j] = (mf == 0.0f) ? hrf[j] : hn;
            }
            __nv_bfloat16 hi0 = __float2bfloat16_rn(hrf[0]);
            __nv_bfloat16 hi1 = __float2bfloat16_rn(hrf[1]);
            __nv_bfloat16 lo0 = __float2bfloat16_rn(hrf[0] - __bfloat162float(hi0));
            __nv_bfloat16 lo1 = __float2bfloat16_rn(hrf[1] - __bfloat162float(hi1));
            __nv_bfloat162 hp = __halves2bfloat162(hi0, hi1);
            __nv_bfloat162 lp = __halves2bfloat162(lo0, lo1);
            ((uint32_t*)&g_hfrag[par ^ 1][0][0][kb_c][mb_c][lane_c])[reg_c] =
                *(uint32_t*)&hp;
            ((uint32_t*)&g_hfrag[par ^ 1][0][1][kb_c][mb_c][lane_c])[reg_c] =
                *(uint32_t*)&lp;
            *(float2*)&out[(((size_t)n_c * SL + posf) * 2 + 0) * HH + hcol] =
                make_float2(hrf[0] * mf, hrf[1] * mf);
            if (t == SL - 1) {
                *(float2*)&out[(size_t)NB * SL * 2 * HH +
                               ((size_t)n_c * 2 + 0) * HH + hcol] =
                    make_float2(hrf[0], hrf[1]);
            }
        }
        __syncthreads();
        if (tid == 0) {
            __threadfence();
            *(volatile int*)&g_flag[0][bid] = t + 1;
        }

        // ================= BACKWARD half =================
        if (tid < NBLK) {
            while (*(volatile int*)&g_flag[1][tid] < t) __nanosleep(32);
            __threadfence();
        }
        __syncthreads();

        recur_gemm(smem, 1, par, bid, kq, nq, cp, lid, acc);

        {
            const int p  = kq * 2 + cp;
            const int fq = lid >> 2;
#pragma unroll
            for (int mt = 0; mt < 2; mt++)
#pragma unroll
                for (int g = 0; g < 2; g++) {
                    int col = (nq * 2 + g) * 8 + (lid & 3) * 2;
                    *(float2*)(smem + PART_OFF(p, mt * 16 + fq, col)) =
                        make_float2(acc[mt][g][0], acc[mt][g][1]);
                    *(float2*)(smem + PART_OFF(p, mt * 16 + fq + 8, col)) =
                        make_float2(acc[mt][g][2], acc[mt][g][3]);
                }
        }
        __syncthreads();

        if (do_cell) {
            float pre[4][2];
#pragma unroll
            for (int g = 0; g < 4; ++g) {
                float2 a2 = xpb[g];
#pragma unroll
                for (int p = 0; p < 8; ++p) {
                    float2 v = *(const float2*)(smem + PART_OFF(p, n_c, g * 8 + jj));
                    a2.x += v.x; a2.y += v.y;
                }
                pre[g][0] = a2.x; pre[g][1] = a2.y;
            }
#pragma unroll
            for (int j = 0; j < 2; ++j) {
                float f  = sigmf(pre[0][j]);
                float ii = sigmf(pre[1][j]);
                float o  = sigmf(pre[2][j]);
                ccb[j] = f * ccb[j] + ii * tanhf(pre[3][j]);
                float hn = o * tanhf(ccb[j]);
                hrb[j] = (mb == 0.0f) ? hrb[j] : hn;
            }
            __nv_bfloat16 hi0 = __float2bfloat16_rn(hrb[0]);
            __nv_bfloat16 hi1 = __float2bfloat16_rn(hrb[1]);
            __nv_bfloat16 lo0 = __float2bfloat16_rn(hrb[0] - __bfloat162float(hi0));
            __nv_bfloat16 lo1 = __float2bfloat16_rn(hrb[1] - __bfloat162float(hi1));
            __nv_bfloat162 hp = __halves2bfloat162(hi0, hi1);
            __nv_bfloat162 lp = __halves2bfloat162(lo0, lo1);
            ((uint32_t*)&g_hfrag[par ^ 1][1][0][kb_c][mb_c][lane_c])[reg_c] =
                *(uint32_t*)&hp;
            ((uint32_t*)&g_hfrag[par ^ 1][1][1][kb_c][mb_c][lane_c])[reg_c] =
                *(uint32_t*)&lp;
            *(float2*)&out[(((size_t)n_c * SL + posb) * 2 + 1) * HH + hcol] =
                make_float2(hrb[0] * mb, hrb[1] * mb);
            if (t == SL - 1) {
                *(float2*)&out[(size_t)NB * SL * 2 * HH +
                               ((size_t)n_c * 2 + 1) * HH + hcol] =
                    make_float2(hrb[0], hrb[1]);
            }
        }
        __syncthreads();
        if (tid == 0) {
            __threadfence();
            *(volatile int*)&g_flag[1][bid] = t + 1;
        }
    }
}

// ---------------------------------------------------------------------------
// Launch
// ---------------------------------------------------------------------------
extern "C" void kernel_launch(void* const* d_in, const int* in_sizes, int n_in,
                              void* d_out, int out_size) {
    const float* x    = (const float*)d_in[0];   // (32,256,1024)
    const float* mask = (const float*)d_in[1];   // (32,256)
    const float* wih  = (const float*)d_in[2];   // (8,1024,1024)
    const float* whh  = (const float*)d_in[3];   // (8,1024,1024)
    const float* bias = (const float*)d_in[4];   // (8,1,1024)
    float* out = (float*)d_out;

    cudaFuncSetAttribute(bilstm_dual,
                         cudaFuncAttributeMaxDynamicSharedMemorySize,
                         SM_TOTAL);

    zero_state_kernel<<<64, 256>>>();
    convert_x_kernel<<<1024, 256>>>(x);
    dim3 wgrid(32, 32, 8);
    convert_w_kernel<<<wgrid, dim3(32, 8)>>>(wih);
    convert_whh_frag_kernel<<<dim3(8, 128), 256>>>(whh);

    dim3 ggrid(64, 16, 8);
    gemm_ih_mma_kernel<<<ggrid, 256>>>(bias);

    bilstm_dual<<<NBLK, TPB, SM_TOTAL>>>(mask, out);
}

// round 13
// speedup vs baseline: 1.2479x; 1.2479x over previous
#include <cuda_runtime.h>
#include <cuda_bf16.h>
#include <math.h>
#include <cstdint>

// Problem constants
#define NB   32      // batch
#define SL   256     // sequence length
#define DD   1024    // input dim
#define HH   1024    // hidden dim
#define NBLK 128     // persistent blocks (2 dir * 64 hc-tiles of 16)
#define DBLK 64      // blocks per direction

// ---------------------------------------------------------------------------
// Scratch (device globals)
// ---------------------------------------------------------------------------
__device__ float g_xh[(size_t)8 * SL * NB * HH];   // 268 MB: xh[g][s][n][h]
// per-block progress flags, each padded to its own 128B L2 line
__device__ int   g_flag[2][DBLK][32];
// bf16 split operands for the input GEMM
__device__ __nv_bfloat16 g_xa_hi[(size_t)NB * SL * DD];
__device__ __nv_bfloat16 g_xa_lo[(size_t)NB * SL * DD];
__device__ __nv_bfloat16 g_wt_hi[(size_t)8 * HH * DD];   // W_ih [g][n][k]
__device__ __nv_bfloat16 g_wt_lo[(size_t)8 * HH * DD];
// W_hh in mma-fragment-major layout: [g(8)][nb(128)][kb(64)][lane(32)] uint2
__device__ uint2 g_wrhifrag[8][128][64][32];
__device__ uint2 g_wrlofrag[8][128][64][32];
// h state in A-fragment-major layout, double-buffered by parity:
//   [par][dir][hl][kb(64)][mb(2)][lane(32)] uint4 (regs a0..a3)
__device__ uint4 g_hfrag[2][2][2][64][2][32];

__device__ __forceinline__ float sigmf(float v) {
    return 1.0f / (1.0f + expf(-v));
}

// mma.sync m16n8k16 bf16, fp32 accumulate
__device__ __forceinline__ void mma16816(float* c, const uint32_t* a,
                                         const uint32_t* b) {
    asm volatile(
        "mma.sync.aligned.m16n8k16.row.col.f32.bf16.bf16.f32 "
        "{%0,%1,%2,%3}, {%4,%5,%6,%7}, {%8,%9}, {%0,%1,%2,%3};"
        : "+f"(c[0]), "+f"(c[1]), "+f"(c[2]), "+f"(c[3])
        : "r"(a[0]), "r"(a[1]), "r"(a[2]), "r"(a[3]), "r"(b[0]), "r"(b[1]));
}

__device__ __forceinline__ void st_release_gpu(int* p, int v) {
    asm volatile("st.release.gpu.global.b32 [%0], %1;" :: "l"(p), "r"(v)
                 : "memory");
}
__device__ __forceinline__ int ld_relaxed_gpu(const int* p) {
    int v;
    asm volatile("ld.relaxed.gpu.global.b32 %0, [%1];" : "=r"(v) : "l"(p)
                 : "memory");
    return v;
}

// ---------------------------------------------------------------------------
// Kernel 0: zero init of h fragments and flags
// ---------------------------------------------------------------------------
__global__ void zero_state_kernel() {
    int idx = blockIdx.x * blockDim.x + threadIdx.x;
    uint4* hf = &g_hfrag[0][0][0][0][0][0];
    int total = 2 * 2 * 2 * 64 * 2 * 32;      // 16384 uint4
    for (int i = idx; i < total; i += gridDim.x * blockDim.x)
        hf[i] = make_uint4(0, 0, 0, 0);
    int* fl = &g_flag[0][0][0];
    for (int i = idx; i < 2 * DBLK * 32; i += gridDim.x * blockDim.x) fl[i] = 0;
}

// ---------------------------------------------------------------------------
// Kernel A: convert x -> bf16 hi/lo
// ---------------------------------------------------------------------------
__global__ __launch_bounds__(256)
void convert_x_kernel(const float* __restrict__ x) {
    const size_t total4 = (size_t)NB * SL * DD / 4;
    for (size_t i = blockIdx.x * 256 + threadIdx.x; i < total4;
         i += (size_t)gridDim.x * 256) {
        float4 v = *(const float4*)(x + i * 4);
        __nv_bfloat16 h0 = __float2bfloat16_rn(v.x);
        __nv_bfloat16 h1 = __float2bfloat16_rn(v.y);
        __nv_bfloat16 h2 = __float2bfloat16_rn(v.z);
        __nv_bfloat16 h3 = __float2bfloat16_rn(v.w);
        __nv_bfloat16 l0 = __float2bfloat16_rn(v.x - __bfloat162float(h0));
        __nv_bfloat16 l1 = __float2bfloat16_rn(v.y - __bfloat162float(h1));
        __nv_bfloat16 l2 = __float2bfloat16_rn(v.z - __bfloat162float(h2));
        __nv_bfloat16 l3 = __float2bfloat16_rn(v.w - __bfloat162float(h3));
        __nv_bfloat162 hh0 = __halves2bfloat162(h0, h1);
        __nv_bfloat162 hh1 = __halves2bfloat162(h2, h3);
        __nv_bfloat162 ll0 = __halves2bfloat162(l0, l1);
        __nv_bfloat162 ll1 = __halves2bfloat162(l2, l3);
        *(uint2*)(g_xa_hi + i * 4) = make_uint2(*(uint32_t*)&hh0, *(uint32_t*)&hh1);
        *(uint2*)(g_xa_lo + i * 4) = make_uint2(*(uint32_t*)&ll0, *(uint32_t*)&ll1);
    }
}

// ---------------------------------------------------------------------------
// Kernel B: transpose + convert W_ih -> [g][n][k] bf16 hi/lo (row-major)
// ---------------------------------------------------------------------------
__global__ void convert_w_kernel(const float* __restrict__ w) {
    __shared__ float tile[32][33];
    const int g  = blockIdx.z;
    const int k0 = blockIdx.x * 32;
    const int n0 = blockIdx.y * 32;
    const int tx = threadIdx.x, ty = threadIdx.y;   // (32, 8)
    const float* W = w + ((size_t)g << 20);
#pragma unroll
    for (int i = 0; i < 4; i++)
        tile[ty + 8 * i][tx] = W[(size_t)(k0 + ty + 8 * i) * HH + n0 + tx];
    __syncthreads();
#pragma unroll
    for (int i = 0; i < 4; i++) {
        float v = tile[tx][ty + 8 * i];
        __nv_bfloat16 hi = __float2bfloat16_rn(v);
        __nv_bfloat16 lo = __float2bfloat16_rn(v - __bfloat162float(hi));
        size_t idx = ((size_t)g << 20) + (size_t)(n0 + ty + 8 * i) * DD + k0 + tx;
        g_wt_hi[idx] = hi;
        g_wt_lo[idx] = lo;
    }
}

// ---------------------------------------------------------------------------
// Kernel B2: W_hh -> fragment-major bf16 hi/lo
// ---------------------------------------------------------------------------
__global__ __launch_bounds__(256)
void convert_whh_frag_kernel(const float* __restrict__ whh) {
    const int g  = blockIdx.x;          // 0..7
    const int nb = blockIdx.y;          // 0..127
    const int tid = threadIdx.x;
    const int nn  = tid & 7;            // row within nb
    const int kp0 = tid >> 3;           // 0..31
    const int n   = nb * 8 + nn;
    const float* W = whh + ((size_t)g << 20);   // [k][n]

    for (int iter = 0; iter < 16; iter++) {
        int kp = iter * 32 + kp0;       // 0..511
        int k  = kp * 2;
        float v0 = W[(size_t)k * HH + n];
        float v1 = W[(size_t)(k + 1) * HH + n];
        __nv_bfloat16 h0 = __float2bfloat16_rn(v0);
        __nv_bfloat16 h1 = __float2bfloat16_rn(v1);
        __nv_bfloat16 l0 = __float2bfloat16_rn(v0 - __bfloat162float(h0));
        __nv_bfloat16 l1 = __float2bfloat16_rn(v1 - __bfloat162float(h1));
        __nv_bfloat162 hp = __halves2bfloat162(h0, h1);
        __nv_bfloat162 lp = __halves2bfloat162(l0, l1);
        int kb   = k >> 4;
        int lane = nn * 4 + ((k & 7) >> 1);
        int reg  = (k >> 3) & 1;
        ((uint32_t*)&g_wrhifrag[g][nb][kb][lane])[reg] = *(uint32_t*)&hp;
        ((uint32_t*)&g_wrlofrag[g][nb][kb][lane])[reg] = *(uint32_t*)&lp;
    }
}

// ---------------------------------------------------------------------------
// Kernel C: mma.sync bf16x3 input-projection GEMM (proven in R6).
// ---------------------------------------------------------------------------
#define ASTR 40

__global__ __launch_bounds__(256, 2)
void gemm_ih_mma_kernel(const float* __restrict__ bias) {
    __shared__ __nv_bfloat16 As_hi[128][ASTR];
    __shared__ __nv_bfloat16 As_lo[128][ASTR];
    __shared__ __nv_bfloat16 Bs_hi[64][ASTR];
    __shared__ __nv_bfloat16 Bs_lo[64][ASTR];

    const int g   = blockIdx.z;
    const int m0  = blockIdx.x * 128;
    const int n0  = blockIdx.y * 64;
    const int tid = threadIdx.x;
    const int wid = tid >> 5;
    const int lid = tid & 31;
    const int wm  = wid & 3;
    const int wn  = wid >> 2;

    const __nv_bfloat16* a_hi = g_xa_hi;
    const __nv_bfloat16* a_lo = g_xa_lo;
    const __nv_bfloat16* b_hi = g_wt_hi + ((size_t)g << 20);
    const __nv_bfloat16* b_lo = g_wt_lo + ((size_t)g << 20);

    float acc[2][4][4];
#pragma unroll
    for (int mt = 0; mt < 2; mt++)
#pragma unroll
        for (int nt = 0; nt < 4; nt++)
#pragma unroll
            for (int r = 0; r < 4; r++) acc[mt][nt][r] = 0.0f;

    const int fq = lid >> 2;
    const int fk = (lid & 3) * 2;

    for (int k0 = 0; k0 < DD; k0 += 32) {
        __syncthreads();
#pragma unroll
        for (int s = 0; s < 2; s++) {
            int lin = tid + s * 256;
            int row = lin >> 2;
            int kq  = (lin & 3) * 8;
            *(uint4*)&As_hi[row][kq] =
                *(const uint4*)(a_hi + (size_t)(m0 + row) * DD + k0 + kq);
            *(uint4*)&As_lo[row][kq] =
                *(const uint4*)(a_lo + (size_t)(m0 + row) * DD + k0 + kq);
        }
        {
            int row = tid >> 2;
            int kq  = (tid & 3) * 8;
            *(uint4*)&Bs_hi[row][kq] =
                *(const uint4*)(b_hi + (size_t)(n0 + row) * DD + k0 + kq);
            *(uint4*)&Bs_lo[row][kq] =
                *(const uint4*)(b_lo + (size_t)(n0 + row) * DD + k0 + kq);
        }
        __syncthreads();

#pragma unroll
        for (int ks = 0; ks < 32; ks += 16) {
            uint32_t Ah[2][4], Al[2][4], Bh[4][2], Bl[4][2];
#pragma unroll
            for (int mt = 0; mt < 2; mt++) {
                int mb = wm * 32 + mt * 16;
                Ah[mt][0] = *(const uint32_t*)&As_hi[mb + fq][ks + fk];
                Ah[mt][1] = *(const uint32_t*)&As_hi[mb + fq + 8][ks + fk];
                Ah[mt][2] = *(const uint32_t*)&As_hi[mb + fq][ks + fk + 8];
                Ah[mt][3] = *(const uint32_t*)&As_hi[mb + fq + 8][ks + fk + 8];
                Al[mt][0] = *(const uint32_t*)&As_lo[mb + fq][ks + fk];
                Al[mt][1] = *(const uint32_t*)&As_lo[mb + fq + 8][ks + fk];
                Al[mt][2] = *(const uint32_t*)&As_lo[mb + fq][ks + fk + 8];
                Al[mt][3] = *(const uint32_t*)&As_lo[mb + fq + 8][ks + fk + 8];
            }
#pragma unroll
            for (int nt = 0; nt < 4; nt++) {
                int nb = wn * 32 + nt * 8;
                Bh[nt][0] = *(const uint32_t*)&Bs_hi[nb + fq][ks + fk];
                Bh[nt][1] = *(const uint32_t*)&Bs_hi[nb + fq][ks + fk + 8];
                Bl[nt][0] = *(const uint32_t*)&Bs_lo[nb + fq][ks + fk];
                Bl[nt][1] = *(const uint32_t*)&Bs_lo[nb + fq][ks + fk + 8];
            }
#pragma unroll
            for (int mt = 0; mt < 2; mt++)
#pragma unroll
                for (int nt = 0; nt < 4; nt++) {
                    mma16816(acc[mt][nt], Ah[mt], Bh[nt]);
                    mma16816(acc[mt][nt], Ah[mt], Bl[nt]);
                    mma16816(acc[mt][nt], Al[mt], Bh[nt]);
                }
        }
    }

#pragma unroll
    for (int mt = 0; mt < 2; mt++) {
#pragma unroll
        for (int nt = 0; nt < 4; nt++) {
            int col = n0 + wn * 32 + nt * 8 + (lid & 3) * 2;
            float2 bz = *(const float2*)&bias[g * HH + col];
#pragma unroll
            for (int half = 0; half < 2; half++) {
                int row  = m0 + wm * 32 + mt * 16 + fq + half * 8;
                int nidx = row >> 8;
                int s    = row & 255;
                size_t base = ((((size_t)g * SL + s) * NB + nidx) << 10) + col;
                *(float2*)&g_xh[base] = make_float2(
                    acc[mt][nt][half * 2 + 0] + bz.x,
                    acc[mt][nt][half * 2 + 1] + bz.y);
            }
        }
    }
}

// ---------------------------------------------------------------------------
// Kernel D: persistent recurrence, zero-staging fragment design (R10 layout)
// with padded-flag release/relaxed barrier (no threadfence, no atomics).
// 128 blocks x 256 threads. Block -> (dir, 16 h-cols x 4 gates).
// ---------------------------------------------------------------------------
// smem: [0,131072) W_hi frags: ((lb*64 + kb)*32 + lane) * 8 bytes
//       [131072, +33792) PART [4][32][66] f32
#define SM_TOTAL 164864
#define WHIF_OFF(lb, kb, lane) ((uint32_t)((((lb) * 64 + (kb)) * 32 + (lane)) * 8))
#define PART_OFF(p, row, col)  ((uint32_t)(131072 + (((p) * 32 + (row)) * 66 + (col)) * 4))

__global__ __launch_bounds__(256, 1)
void bilstm_persistent_mma6(const float* __restrict__ mask,
                            float* __restrict__ out) {
    extern __shared__ char smem[];

    const int bid = blockIdx.x;
    const int dir = bid & 1;
    const int ht  = bid >> 1;             // 0..63 (16-col tile)
    const int tid = threadIdx.x;
    const int wid = tid >> 5;
    const int lid = tid & 31;
    const int kh  = (wid >> 2) & 1;       // K half
    const int nq  = (wid >> 1) & 1;       // 32-col half
    const int cp  = wid & 1;              // kstep parity

    // ---- resident W_hi fragment copy ----
#pragma unroll
    for (int lb = 0; lb < 8; lb++) {
        const uint4* src = (const uint4*)&g_wrhifrag[dir * 4 + (lb >> 1)]
                                                    [ht * 2 + (lb & 1)][0][0];
        uint4* dst = (uint4*)(smem + lb * 16384);
        for (int i = tid; i < 1024; i += 256) dst[i] = src[i];
    }
    __syncthreads();

    // per-warp B row constants
    int dg[4], nbg[4];
#pragma unroll
    for (int nt = 0; nt < 4; nt++) {
        int lb  = nq * 4 + nt;
        dg[nt]  = dir * 4 + (lb >> 1);
        nbg[nt] = ht * 2 + (lb & 1);
    }

    // Cell assignment: thread -> (n, 2 h-cols)
    const int n_c  = tid >> 3;             // 0..31
    const int jj   = (tid & 7) * 2;        // 0..14
    const int hcol = ht * 16 + jj;
    const int lane_c = (n_c & 7) * 4 + ((jj & 7) >> 1);
    const int reg_c  = ((jj >> 3) & 1) * 2 + ((n_c >> 3) & 1);
    const int mb_c   = n_c >> 4;
    float cc[2] = {0.f, 0.f};
    float hr[2] = {0.f, 0.f};
    const float* mrow = mask + n_c * SL;
    const int* my_poll = (tid < DBLK) ? &g_flag[dir][tid][0] : nullptr;

    for (int t = 0; t < SL; t++) {
        const int par = t & 1;
        const int pos = dir ? (SL - 1 - t) : t;

        // Prefetch cell xh + mask
        float2 xpre[4];
#pragma unroll
        for (int g = 0; g < 4; ++g)
            xpre[g] = __ldcg((const float2*)&g_xh[
                ((((size_t)(dir * 4 + g) * SL + pos) * NB + n_c) << 10) + hcol]);
        const float m = mrow[pos];

        float acc[2][4][4];
#pragma unroll
        for (int mt = 0; mt < 2; mt++)
#pragma unroll
            for (int nt = 0; nt < 4; nt++)
#pragma unroll
                for (int r = 0; r < 4; r++) acc[mt][nt][r] = 0.0f;

        // ---- GEMM: 16 ksteps, register-pipelined fragment loads ----
        uint4 Ab[2][2][2];   // [buf][hl][mt]
        uint2 Wb[2][4];      // [buf][nt]

        {
            int kb = kh * 32 + cp;
            Ab[0][0][0] = __ldcg(&g_hfrag[par][dir][0][kb][0][lid]);
            Ab[0][0][1] = __ldcg(&g_hfrag[par][dir][0][kb][1][lid]);
            Ab[0][1][0] = __ldcg(&g_hfrag[par][dir][1][kb][0][lid]);
            Ab[0][1][1] = __ldcg(&g_hfrag[par][dir][1][kb][1][lid]);
#pragma unroll
            for (int nt = 0; nt < 4; nt++)
                Wb[0][nt] = g_wrlofrag[dg[nt]][nbg[nt]][kb][lid];
        }

        for (int j = 0; j < 16; j++) {
            const int b  = j & 1;
            const int kb = kh * 32 + cp + 2 * j;
            if (j < 15) {
                int kb2 = kb + 2;
                Ab[b ^ 1][0][0] = __ldcg(&g_hfrag[par][dir][0][kb2][0][lid]);
                Ab[b ^ 1][0][1] = __ldcg(&g_hfrag[par][dir][0][kb2][1][lid]);
                Ab[b ^ 1][1][0] = __ldcg(&g_hfrag[par][dir][1][kb2][0][lid]);
                Ab[b ^ 1][1][1] = __ldcg(&g_hfrag[par][dir][1][kb2][1][lid]);
#pragma unroll
                for (int nt = 0; nt < 4; nt++)
                    Wb[b ^ 1][nt] = g_wrlofrag[dg[nt]][nbg[nt]][kb2][lid];
            }
#pragma unroll
            for (int nt = 0; nt < 4; nt++) {
                int lb = nq * 4 + nt;
                uint2 Bh = *(const uint2*)(smem + WHIF_OFF(lb, kb, lid));
                const uint32_t* Ah0 = (const uint32_t*)&Ab[b][0][0];
                const uint32_t* Ah1 = (const uint32_t*)&Ab[b][0][1];
                const uint32_t* Al0 = (const uint32_t*)&Ab[b][1][0];
                const uint32_t* Al1 = (const uint32_t*)&Ab[b][1][1];
                uint32_t bh[2] = {Bh.x, Bh.y};
                uint32_t bl[2] = {Wb[b][nt].x, Wb[b][nt].y};
                mma16816(acc[0][nt], Ah0, bh);
                mma16816(acc[1][nt], Ah1, bh);
                mma16816(acc[0][nt], Ah0, bl);
                mma16816(acc[1][nt], Ah1, bl);
                mma16816(acc[0][nt], Al0, bh);
                mma16816(acc[1][nt], Al1, bh);
            }
        }

        // ---- write partials to smem ----
        {
            const int p  = kh * 2 + cp;
            const int fq = lid >> 2;
#pragma unroll
            for (int mt = 0; mt < 2; mt++)
#pragma unroll
                for (int nt = 0; nt < 4; nt++) {
                    int col = nq * 32 + nt * 8 + (lid & 3) * 2;
                    *(float2*)(smem + PART_OFF(p, mt * 16 + fq, col)) =
                        make_float2(acc[mt][nt][0], acc[mt][nt][1]);
                    *(float2*)(smem + PART_OFF(p, mt * 16 + fq + 8, col)) =
                        make_float2(acc[mt][nt][2], acc[mt][nt][3]);
                }
        }
        __syncthreads();

        // ---- cell phase ----
        {
            float pre[4][2];
#pragma unroll
            for (int g = 0; g < 4; ++g) {
                float2 a2 = xpre[g];
#pragma unroll
                for (int p = 0; p < 4; ++p) {
                    float2 v = *(const float2*)(smem + PART_OFF(p, n_c, g * 16 + jj));
                    a2.x += v.x; a2.y += v.y;
                }
                pre[g][0] = a2.x; pre[g][1] = a2.y;
            }
#pragma unroll
            for (int j = 0; j < 2; ++j) {
                float f  = sigmf(pre[0][j]);
                float ii = sigmf(pre[1][j]);
                float o  = sigmf(pre[2][j]);
                cc[j] = f * cc[j] + ii * tanhf(pre[3][j]);
                float hn = o * tanhf(cc[j]);
                hr[j] = (m == 0.0f) ? hr[j] : hn;
            }

            // write h into A-fragment layout (hi + lo) -- .cg stores (L2)
            __nv_bfloat16 hi0 = __float2bfloat16_rn(hr[0]);
            __nv_bfloat16 hi1 = __float2bfloat16_rn(hr[1]);
            __nv_bfloat16 lo0 = __float2bfloat16_rn(hr[0] - __bfloat162float(hi0));
            __nv_bfloat16 lo1 = __float2bfloat16_rn(hr[1] - __bfloat162float(hi1));
            __nv_bfloat162 hp = __halves2bfloat162(hi0, hi1);
            __nv_bfloat162 lp = __halves2bfloat162(lo0, lo1);
            __stcg(((uint32_t*)&g_hfrag[par ^ 1][dir][0][ht][mb_c][lane_c]) + reg_c,
                   *(uint32_t*)&hp);
            __stcg(((uint32_t*)&g_hfrag[par ^ 1][dir][1][ht][mb_c][lane_c]) + reg_c,
                   *(uint32_t*)&lp);

            *(float2*)&out[(((size_t)n_c * SL + pos) * 2 + dir) * HH + hcol] =
                make_float2(hr[0] * m, hr[1] * m);
            if (t == SL - 1) {
                *(float2*)&out[(size_t)NB * SL * 2 * HH +
                               ((size_t)n_c * 2 + dir) * HH + hcol] =
                    make_float2(hr[0], hr[1]);
            }
        }

        // ---- flag barrier: release store + padded relaxed polling ----
        __syncthreads();                        // all h stores issued
        if (tid == 0) {
            st_release_gpu(&g_flag[dir][ht][0], t + 1);   // orders h before flag
        }
        if (tid < DBLK) {
            while (ld_relaxed_gpu(my_poll) < t + 1) __nanosleep(64);
        }
        __syncthreads();
    }
}

// ---------------------------------------------------------------------------
// Launch
// ---------------------------------------------------------------------------
extern "C" void kernel_launch(void* const* d_in, const int* in_sizes, int n_in,
                              void* d_out, int out_size) {
    const float* x    = (const float*)d_in[0];   // (32,256,1024)
    const float* mask = (const float*)d_in[1];   // (32,256)
    const float* wih  = (const float*)d_in[2];   // (8,1024,1024)
    const float* whh  = (const float*)d_in[3];   // (8,1024,1024)
    const float* bias = (const float*)d_in[4];   // (8,1,1024)
    float* out = (float*)d_out;

    cudaFuncSetAttribute(bilstm_persistent_mma6,
                         cudaFuncAttributeMaxDynamicSharedMemorySize,
                         SM_TOTAL);

    zero_state_kernel<<<64, 256>>>();
    convert_x_kernel<<<1024, 256>>>(x);
    dim3 wgrid(32, 32, 8);
    convert_w_kernel<<<wgrid, dim3(32, 8)>>>(wih);
    convert_whh_frag_kernel<<<dim3(8, 128), 256>>>(whh);

    dim3 ggrid(64, 16, 8);
    gemm_ih_mma_kernel<<<ggrid, 256>>>(bias);

    bilstm_persistent_mma6<<<NBLK, 256, SM_TOTAL>>>(mask, out);
}